// round 15
// baseline (speedup 1.0000x reference)
#include <cuda_runtime.h>
#include <cuda_fp16.h>

// BasicRNN B=128, S=8000, H=64 — fused kernel, TWO batches per rec block:
//  rec blocks (bid 0..63): each runs batches (2*bid, 2*bid+1) interleaved in
//       the same 64 threads. W_hh registers are shared; the two independent
//       dependency chains hide each other's LDS/tanh latencies. h stored fp16,
//       STG software-pipelined. Progress published per 320 steps.
//  readout blocks (bid 64..3135): poll progress, chunks ck=0..23 per batch.
//  rec-block tail: warp0/warp1 compute ck=24 for batch A/B, then the
//       deterministic fixed-order final reduce -> out[bA], out[bB].

#define BATCH 128
#define SEQ   8000
#define HID   64
#define CHUNK 1600
#define NCHUNK (SEQ / CHUNK)
#define PUBS  5                 // publishes per chunk (every 320 steps)
#define PGRP  80                // groups per publish window
#define GROUPS (SEQ / 4)        // 2000 groups of 4 timesteps
#define NCHK2 25
#define RCHK  24                // external readout chunks (0..23)
#define GCHK  (GROUPS / NCHK2)  // 80 groups per chunk
#define GWARP (GCHK / 8)        // 10 groups per warp (readout blocks)
#define NREC  64                // rec blocks (2 batches each)

typedef unsigned long long ull;

// h scratch (fp16): [B][GROUPS][HID][4] halves = 131 MB
__device__ __half g_h[(size_t)BATCH * GROUPS * HID * 4];
__device__ float g_pnum[BATCH * NCHK2];
__device__ float g_pden[BATCH * NCHK2];
__device__ volatile unsigned g_prog[BATCH];
__device__ unsigned g_done[BATCH];

__device__ __forceinline__ ull ffma2(ull a, ull b, ull c) {
    ull d;
    asm("fma.rn.f32x2 %0, %1, %2, %3;" : "=l"(d) : "l"(a), "l"(b), "l"(c));
    return d;
}
__device__ __forceinline__ ull fadd2(ull a, ull b) {
    ull d;
    asm("add.rn.f32x2 %0, %1, %2;" : "=l"(d) : "l"(a), "l"(b));
    return d;
}
__device__ __forceinline__ float lo32(ull a) { return __int_as_float((unsigned)a); }
__device__ __forceinline__ float hi32(ull a) { return __int_as_float((unsigned)(a >> 32)); }
__device__ __forceinline__ ull pack2(float lo, float hi) {
    return (ull)__float_as_uint(lo) | ((ull)__float_as_uint(hi) << 32);
}

__device__ __forceinline__ float tanh_hw(float z) {
    float r;
    asm("tanh.approx.f32 %0, %1;" : "=f"(r) : "f"(z));
    return r;
}
__device__ __forceinline__ float sigmoid_tanh(float x) {
    return fmaf(0.5f, tanh_hw(0.5f * x), 0.5f);
}

// readout over fp16 h: gcount groups from base; num/den end up warp-uniform.
__device__ __forceinline__ void readout_groups(
    const uint2* base, int gcount, int lane,
    float f0a, float f0b, float f1a, float f1b, float fb0, float fb1,
    float& num, float& den)
{
    #pragma unroll 2
    for (int i = 0; i < gcount; ++i) {
        const uint2* hg = base + (size_t)i * HID;
        uint2 vA = hg[lane];
        uint2 vB = hg[32 + lane];
        float2 A01 = __half22float2(*(const __half2*)&vA.x);
        float2 A23 = __half22float2(*(const __half2*)&vA.y);
        float2 B01 = __half22float2(*(const __half2*)&vB.x);
        float2 B23 = __half22float2(*(const __half2*)&vB.y);
        float p0[4], p1[4];
        p0[0] = fmaf(f0a, A01.x, f0b * B01.x); p1[0] = fmaf(f1a, A01.x, f1b * B01.x);
        p0[1] = fmaf(f0a, A01.y, f0b * B01.y); p1[1] = fmaf(f1a, A01.y, f1b * B01.y);
        p0[2] = fmaf(f0a, A23.x, f0b * B23.x); p1[2] = fmaf(f1a, A23.x, f1b * B23.x);
        p0[3] = fmaf(f0a, A23.y, f0b * B23.y); p1[3] = fmaf(f1a, A23.y, f1b * B23.y);
        #pragma unroll
        for (int o = 16; o > 0; o >>= 1) {
            #pragma unroll
            for (int j = 0; j < 4; j++) {
                p0[j] += __shfl_xor_sync(0xffffffffu, p0[j], o);
                p1[j] += __shfl_xor_sync(0xffffffffu, p1[j], o);
            }
        }
        #pragma unroll
        for (int j = 0; j < 4; j++) {
            float sel = sigmoid_tanh(p0[j] + fb0);
            float sc  = sigmoid_tanh(p1[j] + fb1);
            den += sel;
            num += sc * sel;
        }
    }
}

__global__ void __launch_bounds__(256, 1)
rnn_fused(const float* __restrict__ x,
          const float* __restrict__ W_ih,
          const float* __restrict__ b_ih,
          const float* __restrict__ W_hh,
          const float* __restrict__ b_hh,
          const float* __restrict__ fc_w,
          const float* __restrict__ fc_b,
          float* __restrict__ out)
{
    const int bid = blockIdx.x;
    const int tid = threadIdx.x;

    if (bid < NREC) {
        // ================= recurrence block: batches bA, bB =================
        if (tid >= 64) return;
        __shared__ __align__(16) float hbA[2][HID];
        __shared__ __align__(16) float hbB[2][HID];
        __shared__ float xsA[CHUNK];
        __shared__ float xsB[CHUNK];
        __shared__ float stail[4];      // [numA, denA, numB, denB]

        const int bA = 2 * bid;
        const int bB = 2 * bid + 1;
        const int r  = tid;             // row 0..63

        ull w2[32];                     // shared weights: one copy for both batches
        {
            const double* wp = (const double*)(W_hh + r * HID);
            #pragma unroll
            for (int i = 0; i < 32; i++) w2[i] = __double_as_longlong(wp[i]);
        }
        const float wih_r  = W_ih[r];
        const float bias_r = b_ih[r] + b_hh[r];

        hbA[0][r] = 0.0f;
        hbB[0][r] = 0.0f;

        const float* xbA = x + (long)bA * SEQ;
        const float* xbB = x + (long)bB * SEQ;
        uint2* hpA = (uint2*)(g_h + (size_t)bA * GROUPS * HID * 4) + r;
        uint2* hpB = (uint2*)(g_h + (size_t)bB * GROUPS * HID * 4) + r;

        __syncthreads();

        unsigned steps_done = 0;
        uint2 pendA, pendB;
        bool  have_pend = false;

        for (int c = 0; c < NCHUNK; ++c) {
            for (int i = r; i < CHUNK; i += 64) {
                xsA[i] = xbA[c * CHUNK + i];
                xsB[i] = xbB[c * CHUNK + i];
            }
            __syncthreads();

            #pragma unroll 1
            for (int p = 0; p < PUBS; ++p) {
                const float* xwA = xsA + p * (PGRP * 4);
                const float* xwB = xsB + p * (PGRP * 4);
                #pragma unroll 1
                for (int g = 0; g < PGRP; ++g) {
                    if (have_pend) {            // drain prev group in issue shadow
                        *hpA = pendA; hpA += HID;
                        *hpB = pendB; hpB += HID;
                    }
                    have_pend = true;

                    unsigned hqA[2], hqB[2];
                    #pragma unroll
                    for (int u = 0; u < 4; u += 2) {
                        float hAlo, hAhi, hBlo, hBhi;
                        #pragma unroll
                        for (int v = 0; v < 2; ++v) {
                            const int uu = u + v;
                            const float* hsA = hbA[uu & 1];
                            const float* hsB = hbB[uu & 1];
                            float* hdA = hbA[(uu & 1) ^ 1];
                            float* hdB = hbB[(uu & 1) ^ 1];

                            const float xpA = fmaf(xwA[g * 4 + uu], wih_r, bias_r);
                            const float xpB = fmaf(xwB[g * 4 + uu], wih_r, bias_r);

                            const double2* h2A = (const double2*)hsA;
                            const double2* h2B = (const double2*)hsB;
                            ull aA0 = pack2(xpA, 0.0f), aA1 = 0ull, aA2 = 0ull, aA3 = 0ull;
                            ull aB0 = pack2(xpB, 0.0f), aB1 = 0ull, aB2 = 0ull, aB3 = 0ull;
                            #pragma unroll
                            for (int i = 0; i < 8; i++) {
                                double2 vaA = h2A[2 * i];
                                double2 vbA = h2A[2 * i + 1];
                                double2 vaB = h2B[2 * i];
                                double2 vbB = h2B[2 * i + 1];
                                aA0 = ffma2(w2[4 * i + 0], __double_as_longlong(vaA.x), aA0);
                                aB0 = ffma2(w2[4 * i + 0], __double_as_longlong(vaB.x), aB0);
                                aA1 = ffma2(w2[4 * i + 1], __double_as_longlong(vaA.y), aA1);
                                aB1 = ffma2(w2[4 * i + 1], __double_as_longlong(vaB.y), aB1);
                                aA2 = ffma2(w2[4 * i + 2], __double_as_longlong(vbA.x), aA2);
                                aB2 = ffma2(w2[4 * i + 2], __double_as_longlong(vbB.x), aB2);
                                aA3 = ffma2(w2[4 * i + 3], __double_as_longlong(vbA.y), aA3);
                                aB3 = ffma2(w2[4 * i + 3], __double_as_longlong(vbB.y), aB3);
                            }
                            ull tA = fadd2(fadd2(aA0, aA1), fadd2(aA2, aA3));
                            ull tB = fadd2(fadd2(aB0, aB1), fadd2(aB2, aB3));
                            float zA = lo32(tA) + hi32(tA);
                            float zB = lo32(tB) + hi32(tB);
                            float hA = tanh_hw(zA);
                            float hB = tanh_hw(zB);

                            hdA[r] = hA;
                            hdB[r] = hB;
                            if (v == 0) { hAlo = hA; hBlo = hB; }
                            else        { hAhi = hA; hBhi = hB; }
                            __syncthreads();
                        }
                        __half2 ha = __floats2half2_rn(hAlo, hAhi);
                        __half2 hb = __floats2half2_rn(hBlo, hBhi);
                        hqA[u >> 1] = *(unsigned*)&ha;
                        hqB[u >> 1] = *(unsigned*)&hb;
                    }
                    pendA.x = hqA[0]; pendA.y = hqA[1];
                    pendB.x = hqB[0]; pendB.y = hqB[1];
                }
                if (have_pend) {
                    *hpA = pendA; hpA += HID;
                    *hpB = pendB; hpB += HID;
                    have_pend = false;
                }
                steps_done += PGRP * 4;
                __syncthreads();
                if (r == 0) {
                    __threadfence();
                    g_prog[bA] = steps_done;
                    g_prog[bB] = steps_done;
                }
            }
        }

        // ===== tail: warp0 -> bA ck=24, warp1 -> bB ck=24, then reduces =====
        {
            const int w    = tid >> 5;       // 0..1
            const int lane = tid & 31;
            const int bt   = (w == 0) ? bA : bB;
            const float f0a = fc_w[lane];       const float f0b = fc_w[32 + lane];
            const float f1a = fc_w[64 + lane];  const float f1b = fc_w[96 + lane];
            const float fb0 = fc_b[0];          const float fb1 = fc_b[1];

            const uint2* base = (const uint2*)(g_h +
                ((size_t)bt * GROUPS + (size_t)RCHK * GCHK) * HID * 4);

            float num = 0.0f, den = 0.0f;
            readout_groups(base, GCHK, lane, f0a, f0b, f1a, f1b, fb0, fb1, num, den);

            if (lane == 0) { stail[2 * w] = num; stail[2 * w + 1] = den; }
            __syncthreads();

            if (lane == 0) {                 // tid 0 -> bA, tid 32 -> bB
                float N24 = stail[2 * w];
                float D24 = stail[2 * w + 1];
                while (((volatile unsigned*)g_done)[bt] < RCHK) __nanosleep(256);
                __threadfence();
                float N = 0.0f, D = 0.0f;
                #pragma unroll
                for (int i = 0; i < RCHK; i++) {
                    N += __ldcg(&g_pnum[bt * NCHK2 + i]);
                    D += __ldcg(&g_pden[bt * NCHK2 + i]);
                }
                out[bt] = __fdividef(N + N24, D + D24);
                g_done[bt] = 0u;
                g_prog[bt] = 0u;
            }
        }
    } else {
        // ================= readout block (chunks 0..23) =================
        __shared__ float snum[8], sden[8];

        const int bk   = bid - NREC;
        const int ck   = bk / BATCH;             // 0..23
        const int b    = bk % BATCH;
        const int w    = tid >> 5;
        const int lane = tid & 31;

        const unsigned need = (unsigned)((ck + 1) * GCHK * 4);   // <= 7680
        if (tid == 0) {
            while (g_prog[b] < need) __nanosleep(1024);
        }
        __syncthreads();
        __threadfence();

        const float f0a = fc_w[lane];       const float f0b = fc_w[32 + lane];
        const float f1a = fc_w[64 + lane];  const float f1b = fc_w[96 + lane];
        const float fb0 = fc_b[0];          const float fb1 = fc_b[1];

        const uint2* base = (const uint2*)(g_h +
            ((size_t)b * GROUPS + (size_t)ck * GCHK + (size_t)w * GWARP) * HID * 4);

        float num = 0.0f, den = 0.0f;
        readout_groups(base, GWARP, lane, f0a, f0b, f1a, f1b, fb0, fb1, num, den);

        if (lane == 0) { snum[w] = num; sden[w] = den; }
        __syncthreads();
        if (tid == 0) {
            float N = 0.0f, D = 0.0f;
            #pragma unroll
            for (int i = 0; i < 8; i++) { N += snum[i]; D += sden[i]; }
            g_pnum[b * NCHK2 + ck] = N;
            g_pden[b * NCHK2 + ck] = D;
            __threadfence();
            atomicAdd(&g_done[b], 1u);
        }
    }
}

extern "C" void kernel_launch(void* const* d_in, const int* in_sizes, int n_in,
                              void* d_out, int out_size) {
    const float* x    = (const float*)d_in[0];
    const float* W_ih = (const float*)d_in[1];
    const float* b_ih = (const float*)d_in[2];
    const float* W_hh = (const float*)d_in[3];
    const float* b_hh = (const float*)d_in[4];
    const float* fc_w = (const float*)d_in[5];
    const float* fc_b = (const float*)d_in[6];
    float* out = (float*)d_out;
    (void)in_sizes; (void)n_in; (void)out_size;

    rnn_fused<<<NREC + BATCH * RCHK, 256>>>(x, W_ih, b_ih, W_hh, b_hh, fc_w, fc_b, out);
}

// round 16
// speedup vs baseline: 1.4950x; 1.4950x over previous
#include <cuda_runtime.h>
#include <cuda_fp16.h>

// BasicRNN B=128, S=8000, H=64 — single fused kernel (R14 rec loop, leaner readout):
//  rec blocks (bid 0..127): recurrence, 64 active threads; h=tanh(z) stored fp16,
//       STG software-pipelined one group behind. Progress published every 320
//       steps at loop boundaries. Tail: same block computes ck=24 + final reduce.
//  readout blocks (bid 128..1663): each handles a PAIR of chunks (2j,2j+1) for
//       one batch — half the pollers/launches of the previous grid. Adaptive
//       poll backoff keeps L2 quiet while far from the needed step.

#define BATCH 128
#define SEQ   8000
#define HID   64
#define CHUNK 1600
#define NCHUNK (SEQ / CHUNK)
#define PUBS  5                 // publishes per chunk (every 320 steps)
#define PGRP  80                // groups per publish window
#define GROUPS (SEQ / 4)        // 2000 groups of 4 timesteps
#define GCHK  80                // groups per 320-step chunk
#define RSLOT 12                // readout pair-blocks per batch (chunks 0..23)
#define GPAIR (2 * GCHK)        // 160 groups per readout block
#define GWARP (GPAIR / 8)       // 20 groups per warp
#define RCHK24 24               // rec-tail chunk index

typedef unsigned long long ull;

// h scratch (fp16): [B][GROUPS][HID][4] halves = 131 MB
__device__ __half g_h[(size_t)BATCH * GROUPS * HID * 4];
__device__ float g_pnum[BATCH * RSLOT];
__device__ float g_pden[BATCH * RSLOT];
__device__ volatile unsigned g_prog[BATCH];   // steps completed per batch
__device__ unsigned g_done[BATCH];            // pair-blocks completed

__device__ __forceinline__ ull ffma2(ull a, ull b, ull c) {
    ull d;
    asm("fma.rn.f32x2 %0, %1, %2, %3;" : "=l"(d) : "l"(a), "l"(b), "l"(c));
    return d;
}
__device__ __forceinline__ ull fadd2(ull a, ull b) {
    ull d;
    asm("add.rn.f32x2 %0, %1, %2;" : "=l"(d) : "l"(a), "l"(b));
    return d;
}
__device__ __forceinline__ float lo32(ull a) { return __int_as_float((unsigned)a); }
__device__ __forceinline__ float hi32(ull a) { return __int_as_float((unsigned)(a >> 32)); }
__device__ __forceinline__ ull pack2(float lo, float hi) {
    return (ull)__float_as_uint(lo) | ((ull)__float_as_uint(hi) << 32);
}

__device__ __forceinline__ float tanh_hw(float z) {        // MUFU.TANH
    float r;
    asm("tanh.approx.f32 %0, %1;" : "=f"(r) : "f"(z));
    return r;
}
__device__ __forceinline__ float sigmoid_tanh(float x) {   // 1 MUFU
    return fmaf(0.5f, tanh_hw(0.5f * x), 0.5f);
}

// readout inner body over fp16 h: `gcount` groups from base row pointer.
__device__ __forceinline__ void readout_groups(
    const uint2* base, int gcount, int lane,
    float f0a, float f0b, float f1a, float f1b, float fb0, float fb1,
    float& num, float& den)
{
    #pragma unroll 2
    for (int i = 0; i < gcount; ++i) {
        const uint2* hg = base + (size_t)i * HID;
        uint2 vA = hg[lane];                 // rows 0..31: 4 fp16 steps
        uint2 vB = hg[32 + lane];            // rows 32..63
        float2 A01 = __half22float2(*(const __half2*)&vA.x);
        float2 A23 = __half22float2(*(const __half2*)&vA.y);
        float2 B01 = __half22float2(*(const __half2*)&vB.x);
        float2 B23 = __half22float2(*(const __half2*)&vB.y);
        float p0[4], p1[4];
        p0[0] = fmaf(f0a, A01.x, f0b * B01.x); p1[0] = fmaf(f1a, A01.x, f1b * B01.x);
        p0[1] = fmaf(f0a, A01.y, f0b * B01.y); p1[1] = fmaf(f1a, A01.y, f1b * B01.y);
        p0[2] = fmaf(f0a, A23.x, f0b * B23.x); p1[2] = fmaf(f1a, A23.x, f1b * B23.x);
        p0[3] = fmaf(f0a, A23.y, f0b * B23.y); p1[3] = fmaf(f1a, A23.y, f1b * B23.y);
        #pragma unroll
        for (int o = 16; o > 0; o >>= 1) {
            #pragma unroll
            for (int j = 0; j < 4; j++) {
                p0[j] += __shfl_xor_sync(0xffffffffu, p0[j], o);
                p1[j] += __shfl_xor_sync(0xffffffffu, p1[j], o);
            }
        }
        #pragma unroll
        for (int j = 0; j < 4; j++) {
            float sel = sigmoid_tanh(p0[j] + fb0);
            float sc  = sigmoid_tanh(p1[j] + fb1);
            den += sel;
            num += sc * sel;
        }
    }
}

// ---------------- fused recurrence + overlapped readout + in-kernel finish ----------------
__global__ void __launch_bounds__(256, 1)
rnn_fused(const float* __restrict__ x,      // [B, S]
          const float* __restrict__ W_ih,   // [H, 1]
          const float* __restrict__ b_ih,   // [H]
          const float* __restrict__ W_hh,   // [H, H]
          const float* __restrict__ b_hh,   // [H]
          const float* __restrict__ fc_w,   // [2, H]
          const float* __restrict__ fc_b,   // [2]
          float* __restrict__ out)          // [B]
{
    const int bid = blockIdx.x;
    const int tid = threadIdx.x;

    if (bid < BATCH) {
        // ================= recurrence block (R14 hot loop, unchanged) =================
        if (tid >= 64) return;           // 64 active threads, 2 warps
        __shared__ __align__(16) float hb[2][HID];
        __shared__ float xs[CHUNK];
        __shared__ float snum2[2], sden2[2];

        const int b = bid;
        const int r = tid;               // row 0..63

        ull w2[32];                      // full W_hh row, packed f32x2
        {
            const double* wp = (const double*)(W_hh + r * HID);
            #pragma unroll
            for (int i = 0; i < 32; i++) w2[i] = __double_as_longlong(wp[i]);
        }
        const float wih_r  = W_ih[r];
        const float bias_r = b_ih[r] + b_hh[r];

        hb[0][r] = 0.0f;   // h_0

        const float* xb = x + (long)b * SEQ;
        uint2* hp = (uint2*)(g_h + (size_t)b * GROUPS * HID * 4) + r;

        __syncthreads();

        unsigned steps_done = 0;
        uint2 pend;                      // software-pipelined scratch store
        bool  have_pend = false;

        for (int c = 0; c < NCHUNK; ++c) {
            for (int i = r; i < CHUNK; i += 64)
                xs[i] = xb[c * CHUNK + i];
            __syncthreads();

            #pragma unroll 1
            for (int p = 0; p < PUBS; ++p) {
                const float* xw = xs + p * (PGRP * 4);
                #pragma unroll 1
                for (int g = 0; g < PGRP; ++g) {
                    if (have_pend) {          // drain prev group in issue shadow
                        *hp = pend;
                        hp += HID;
                    }
                    have_pend = true;

                    float xp[4];
                    #pragma unroll
                    for (int u = 0; u < 4; ++u)
                        xp[u] = fmaf(xw[g * 4 + u], wih_r, bias_r);

                    unsigned hq16[2];
                    #pragma unroll
                    for (int u = 0; u < 4; u += 2) {
                        float hlo, hhi;
                        #pragma unroll
                        for (int v = 0; v < 2; ++v) {
                            const int uu = u + v;
                            const float* hsrc = hb[uu & 1];
                            float*       hdst = hb[(uu & 1) ^ 1];

                            const double2* h2 = (const double2*)hsrc;  // broadcast
                            ull a0 = pack2(xp[uu], 0.0f);
                            ull a1 = 0ull, a2 = 0ull, a3 = 0ull;
                            #pragma unroll
                            for (int i = 0; i < 8; i++) {
                                double2 va = h2[2 * i];
                                double2 vb = h2[2 * i + 1];
                                a0 = ffma2(w2[4 * i + 0], __double_as_longlong(va.x), a0);
                                a1 = ffma2(w2[4 * i + 1], __double_as_longlong(va.y), a1);
                                a2 = ffma2(w2[4 * i + 2], __double_as_longlong(vb.x), a2);
                                a3 = ffma2(w2[4 * i + 3], __double_as_longlong(vb.y), a3);
                            }
                            ull tS = fadd2(fadd2(a0, a1), fadd2(a2, a3));
                            float z = lo32(tS) + hi32(tS);
                            float h = tanh_hw(z);

                            hdst[r] = h;             // STS first: serial path
                            if (v == 0) hlo = h; else hhi = h;
                            __syncthreads();
                        }
                        __half2 hh = __floats2half2_rn(hlo, hhi);   // tail shadow
                        hq16[u >> 1] = *(unsigned*)&hh;
                    }
                    pend.x = hq16[0];
                    pend.y = hq16[1];
                }
                if (have_pend) {
                    *hp = pend;
                    hp += HID;
                    have_pend = false;
                }
                steps_done += PGRP * 4;
                __syncthreads();                // order all threads' group STGs
                if (r == 0) {
                    __threadfence();
                    g_prog[b] = steps_done;
                }
            }
        }

        // ===== tail: compute own batch's last chunk (ck=24) + final reduce =====
        {
            const int w    = tid >> 5;       // 0..1
            const int lane = tid & 31;
            const float f0a = fc_w[lane];       const float f0b = fc_w[32 + lane];
            const float f1a = fc_w[64 + lane];  const float f1b = fc_w[96 + lane];
            const float fb0 = fc_b[0];          const float fb1 = fc_b[1];

            const uint2* base = (const uint2*)(g_h +
                ((size_t)b * GROUPS + (size_t)RCHK24 * GCHK + (size_t)w * (GCHK / 2)) * HID * 4);

            float num = 0.0f, den = 0.0f;
            readout_groups(base, GCHK / 2, lane, f0a, f0b, f1a, f1b, fb0, fb1, num, den);

            if (lane == 0) { snum2[w] = num; sden2[w] = den; }
            __syncthreads();

            if (tid == 0) {
                float N24 = snum2[0] + snum2[1];
                float D24 = sden2[0] + sden2[1];
                while (((volatile unsigned*)g_done)[b] < RSLOT) __nanosleep(256);
                __threadfence();
                float N = 0.0f, D = 0.0f;
                #pragma unroll
                for (int i = 0; i < RSLOT; i++) {         // fixed order: deterministic
                    N += __ldcg(&g_pnum[b * RSLOT + i]);
                    D += __ldcg(&g_pden[b * RSLOT + i]);
                }
                out[b] = __fdividef(N + N24, D + D24);
                g_done[b] = 0u;                           // reset for replay
                g_prog[b] = 0u;
            }
        }
    } else {
        // ================= readout pair-block (chunks 2j, 2j+1) =================
        __shared__ float snum[8], sden[8];

        const int bk   = bid - BATCH;
        const int j    = bk / BATCH;             // 0..11, pair index (ck-major)
        const int b    = bk % BATCH;
        const int w    = tid >> 5;
        const int lane = tid & 31;

        const unsigned need = (unsigned)((2 * j + 2) * GCHK * 4);   // <= 7680
        if (tid == 0) {
            unsigned cur;
            while ((cur = g_prog[b]) < need) {
                unsigned lag = need - cur;
                __nanosleep(lag > 960 ? 8192 : 1024);    // adaptive backoff
            }
        }
        __syncthreads();
        __threadfence();                         // acquire side

        const float f0a = fc_w[lane];       const float f0b = fc_w[32 + lane];
        const float f1a = fc_w[64 + lane];  const float f1b = fc_w[96 + lane];
        const float fb0 = fc_b[0];          const float fb1 = fc_b[1];

        const uint2* base = (const uint2*)(g_h +
            ((size_t)b * GROUPS + (size_t)(2 * j) * GCHK + (size_t)w * GWARP) * HID * 4);

        float num = 0.0f, den = 0.0f;
        readout_groups(base, GWARP, lane, f0a, f0b, f1a, f1b, fb0, fb1, num, den);

        if (lane == 0) { snum[w] = num; sden[w] = den; }
        __syncthreads();
        if (tid == 0) {
            float N = 0.0f, D = 0.0f;
            #pragma unroll
            for (int i = 0; i < 8; i++) { N += snum[i]; D += sden[i]; }
            g_pnum[b * RSLOT + j] = N;
            g_pden[b * RSLOT + j] = D;
            __threadfence();                     // release partials before count
            atomicAdd(&g_done[b], 1u);
        }
    }
}

extern "C" void kernel_launch(void* const* d_in, const int* in_sizes, int n_in,
                              void* d_out, int out_size) {
    const float* x    = (const float*)d_in[0];
    const float* W_ih = (const float*)d_in[1];
    const float* b_ih = (const float*)d_in[2];
    const float* W_hh = (const float*)d_in[3];
    const float* b_hh = (const float*)d_in[4];
    const float* fc_w = (const float*)d_in[5];
    const float* fc_b = (const float*)d_in[6];
    float* out = (float*)d_out;
    (void)in_sizes; (void)n_in; (void)out_size;

    rnn_fused<<<BATCH + BATCH * RSLOT, 256>>>(x, W_ih, b_ih, W_hh, b_hh, fc_w, fc_b, out);
}

// round 17
// speedup vs baseline: 1.5823x; 1.0584x over previous
#include <cuda_runtime.h>
#include <cuda_fp16.h>

// BasicRNN B=128, S=8000, H=64 — single fused kernel (R14 configuration):
//  rec blocks (bid 0..127): recurrence, 64 active threads; h=tanh(z) stored fp16,
//       STG software-pipelined one group behind (issued in the next group's
//       FFMA-issue shadow). Progress published every 320 steps at loop
//       boundaries. Tail: same block computes ck=24 + deterministic reduce.
//  readout blocks (bid 128..3199): one 320-step chunk each (ck 0..23), ck-major;
//       adaptive poll backoff (coarse sleep while far from the needed step).

#define BATCH 128
#define SEQ   8000
#define HID   64
#define CHUNK 1600
#define NCHUNK (SEQ / CHUNK)
#define PUBS  5                 // publishes per chunk (every 320 steps)
#define PGRP  80                // groups per publish window
#define GROUPS (SEQ / 4)        // 2000 groups of 4 timesteps
#define NCHK2 25                // total partial slots per batch
#define RCHK  24                // chunks handled by readout blocks (0..23)
#define GCHK  (GROUPS / NCHK2)  // 80 groups per chunk (320 steps)
#define GWARP (GCHK / 8)        // 10 groups per warp (readout blocks)

typedef unsigned long long ull;

// h scratch (fp16): [B][GROUPS][HID][4] halves = 131 MB
__device__ __half g_h[(size_t)BATCH * GROUPS * HID * 4];
__device__ float g_pnum[BATCH * NCHK2];
__device__ float g_pden[BATCH * NCHK2];
__device__ volatile unsigned g_prog[BATCH];   // steps completed per batch
__device__ unsigned g_done[BATCH];            // readout chunks completed

__device__ __forceinline__ ull ffma2(ull a, ull b, ull c) {
    ull d;
    asm("fma.rn.f32x2 %0, %1, %2, %3;" : "=l"(d) : "l"(a), "l"(b), "l"(c));
    return d;
}
__device__ __forceinline__ ull fadd2(ull a, ull b) {
    ull d;
    asm("add.rn.f32x2 %0, %1, %2;" : "=l"(d) : "l"(a), "l"(b));
    return d;
}
__device__ __forceinline__ float lo32(ull a) { return __int_as_float((unsigned)a); }
__device__ __forceinline__ float hi32(ull a) { return __int_as_float((unsigned)(a >> 32)); }
__device__ __forceinline__ ull pack2(float lo, float hi) {
    return (ull)__float_as_uint(lo) | ((ull)__float_as_uint(hi) << 32);
}

__device__ __forceinline__ float tanh_hw(float z) {        // MUFU.TANH
    float r;
    asm("tanh.approx.f32 %0, %1;" : "=f"(r) : "f"(z));
    return r;
}
__device__ __forceinline__ float sigmoid_tanh(float x) {   // 1 MUFU
    return fmaf(0.5f, tanh_hw(0.5f * x), 0.5f);
}

// readout inner body over fp16 h: `gcount` groups from base row pointer.
__device__ __forceinline__ void readout_groups(
    const uint2* base, int gcount, int lane,
    float f0a, float f0b, float f1a, float f1b, float fb0, float fb1,
    float& num, float& den)
{
    #pragma unroll 2
    for (int i = 0; i < gcount; ++i) {
        const uint2* hg = base + (size_t)i * HID;
        uint2 vA = hg[lane];                 // rows 0..31: 4 fp16 steps
        uint2 vB = hg[32 + lane];            // rows 32..63
        float2 A01 = __half22float2(*(const __half2*)&vA.x);
        float2 A23 = __half22float2(*(const __half2*)&vA.y);
        float2 B01 = __half22float2(*(const __half2*)&vB.x);
        float2 B23 = __half22float2(*(const __half2*)&vB.y);
        float p0[4], p1[4];
        p0[0] = fmaf(f0a, A01.x, f0b * B01.x); p1[0] = fmaf(f1a, A01.x, f1b * B01.x);
        p0[1] = fmaf(f0a, A01.y, f0b * B01.y); p1[1] = fmaf(f1a, A01.y, f1b * B01.y);
        p0[2] = fmaf(f0a, A23.x, f0b * B23.x); p1[2] = fmaf(f1a, A23.x, f1b * B23.x);
        p0[3] = fmaf(f0a, A23.y, f0b * B23.y); p1[3] = fmaf(f1a, A23.y, f1b * B23.y);
        #pragma unroll
        for (int o = 16; o > 0; o >>= 1) {
            #pragma unroll
            for (int j = 0; j < 4; j++) {
                p0[j] += __shfl_xor_sync(0xffffffffu, p0[j], o);
                p1[j] += __shfl_xor_sync(0xffffffffu, p1[j], o);
            }
        }
        #pragma unroll
        for (int j = 0; j < 4; j++) {
            float sel = sigmoid_tanh(p0[j] + fb0);
            float sc  = sigmoid_tanh(p1[j] + fb1);
            den += sel;
            num += sc * sel;
        }
    }
}

// ---------------- fused recurrence + overlapped readout + in-kernel finish ----------------
__global__ void __launch_bounds__(256, 1)
rnn_fused(const float* __restrict__ x,      // [B, S]
          const float* __restrict__ W_ih,   // [H, 1]
          const float* __restrict__ b_ih,   // [H]
          const float* __restrict__ W_hh,   // [H, H]
          const float* __restrict__ b_hh,   // [H]
          const float* __restrict__ fc_w,   // [2, H]
          const float* __restrict__ fc_b,   // [2]
          float* __restrict__ out)          // [B]
{
    const int bid = blockIdx.x;
    const int tid = threadIdx.x;

    if (bid < BATCH) {
        // ================= recurrence block (R14 hot loop, unchanged) =================
        if (tid >= 64) return;           // 64 active threads, 2 warps
        __shared__ __align__(16) float hb[2][HID];
        __shared__ float xs[CHUNK];
        __shared__ float snum2[2], sden2[2];

        const int b = bid;
        const int r = tid;               // row 0..63

        ull w2[32];                      // full W_hh row, packed f32x2
        {
            const double* wp = (const double*)(W_hh + r * HID);
            #pragma unroll
            for (int i = 0; i < 32; i++) w2[i] = __double_as_longlong(wp[i]);
        }
        const float wih_r  = W_ih[r];
        const float bias_r = b_ih[r] + b_hh[r];

        hb[0][r] = 0.0f;   // h_0

        const float* xb = x + (long)b * SEQ;
        uint2* hp = (uint2*)(g_h + (size_t)b * GROUPS * HID * 4) + r;

        __syncthreads();

        unsigned steps_done = 0;
        uint2 pend;                      // software-pipelined scratch store
        bool  have_pend = false;

        for (int c = 0; c < NCHUNK; ++c) {
            for (int i = r; i < CHUNK; i += 64)
                xs[i] = xb[c * CHUNK + i];
            __syncthreads();

            #pragma unroll 1
            for (int p = 0; p < PUBS; ++p) {
                const float* xw = xs + p * (PGRP * 4);
                #pragma unroll 1
                for (int g = 0; g < PGRP; ++g) {
                    if (have_pend) {          // drain prev group in issue shadow
                        *hp = pend;
                        hp += HID;
                    }
                    have_pend = true;

                    float xp[4];
                    #pragma unroll
                    for (int u = 0; u < 4; ++u)
                        xp[u] = fmaf(xw[g * 4 + u], wih_r, bias_r);

                    unsigned hq16[2];
                    #pragma unroll
                    for (int u = 0; u < 4; u += 2) {
                        float hlo, hhi;
                        #pragma unroll
                        for (int v = 0; v < 2; ++v) {
                            const int uu = u + v;
                            const float* hsrc = hb[uu & 1];
                            float*       hdst = hb[(uu & 1) ^ 1];

                            const double2* h2 = (const double2*)hsrc;  // broadcast
                            ull a0 = pack2(xp[uu], 0.0f);
                            ull a1 = 0ull, a2 = 0ull, a3 = 0ull;
                            #pragma unroll
                            for (int i = 0; i < 8; i++) {
                                double2 va = h2[2 * i];
                                double2 vb = h2[2 * i + 1];
                                a0 = ffma2(w2[4 * i + 0], __double_as_longlong(va.x), a0);
                                a1 = ffma2(w2[4 * i + 1], __double_as_longlong(va.y), a1);
                                a2 = ffma2(w2[4 * i + 2], __double_as_longlong(vb.x), a2);
                                a3 = ffma2(w2[4 * i + 3], __double_as_longlong(vb.y), a3);
                            }
                            ull tS = fadd2(fadd2(a0, a1), fadd2(a2, a3));
                            float z = lo32(tS) + hi32(tS);
                            float h = tanh_hw(z);

                            hdst[r] = h;             // STS first: serial path
                            if (v == 0) hlo = h; else hhi = h;
                            __syncthreads();
                        }
                        __half2 hh = __floats2half2_rn(hlo, hhi);   // tail shadow
                        hq16[u >> 1] = *(unsigned*)&hh;
                    }
                    pend.x = hq16[0];
                    pend.y = hq16[1];
                }
                if (have_pend) {
                    *hp = pend;
                    hp += HID;
                    have_pend = false;
                }
                steps_done += PGRP * 4;
                __syncthreads();                // order all threads' group STGs
                if (r == 0) {
                    __threadfence();
                    g_prog[b] = steps_done;
                }
            }
        }

        // ===== tail: compute own batch's last chunk (ck=24) + final reduce =====
        {
            const int w    = tid >> 5;       // 0..1
            const int lane = tid & 31;
            const float f0a = fc_w[lane];       const float f0b = fc_w[32 + lane];
            const float f1a = fc_w[64 + lane];  const float f1b = fc_w[96 + lane];
            const float fb0 = fc_b[0];          const float fb1 = fc_b[1];

            const uint2* base = (const uint2*)(g_h +
                ((size_t)b * GROUPS + (size_t)RCHK * GCHK + (size_t)w * (GCHK / 2)) * HID * 4);

            float num = 0.0f, den = 0.0f;
            readout_groups(base, GCHK / 2, lane, f0a, f0b, f1a, f1b, fb0, fb1, num, den);

            if (lane == 0) { snum2[w] = num; sden2[w] = den; }
            __syncthreads();

            if (tid == 0) {
                float N24 = snum2[0] + snum2[1];
                float D24 = sden2[0] + sden2[1];
                while (((volatile unsigned*)g_done)[b] < RCHK) __nanosleep(256);
                __threadfence();
                float N = 0.0f, D = 0.0f;
                #pragma unroll
                for (int i = 0; i < RCHK; i++) {          // fixed order: deterministic
                    N += __ldcg(&g_pnum[b * NCHK2 + i]);
                    D += __ldcg(&g_pden[b * NCHK2 + i]);
                }
                out[b] = __fdividef(N + N24, D + D24);
                g_done[b] = 0u;                           // reset for replay
                g_prog[b] = 0u;
            }
        }
    } else {
        // ================= readout block (one chunk, ck 0..23) =================
        __shared__ float snum[8], sden[8];

        const int bk   = bid - BATCH;
        const int ck   = bk / BATCH;             // 0..23, ck-major ordering
        const int b    = bk % BATCH;
        const int w    = tid >> 5;
        const int lane = tid & 31;

        const unsigned need = (unsigned)((ck + 1) * GCHK * 4);   // <= 7680
        if (tid == 0) {
            unsigned cur;
            while ((cur = g_prog[b]) < need) {
                unsigned lag = need - cur;
                __nanosleep(lag > 960 ? 8192 : 1024);    // adaptive backoff
            }
        }
        __syncthreads();
        __threadfence();                         // acquire side

        const float f0a = fc_w[lane];       const float f0b = fc_w[32 + lane];
        const float f1a = fc_w[64 + lane];  const float f1b = fc_w[96 + lane];
        const float fb0 = fc_b[0];          const float fb1 = fc_b[1];

        const uint2* base = (const uint2*)(g_h +
            ((size_t)b * GROUPS + (size_t)ck * GCHK + (size_t)w * GWARP) * HID * 4);

        float num = 0.0f, den = 0.0f;
        readout_groups(base, GWARP, lane, f0a, f0b, f1a, f1b, fb0, fb1, num, den);

        if (lane == 0) { snum[w] = num; sden[w] = den; }
        __syncthreads();
        if (tid == 0) {
            float N = 0.0f, D = 0.0f;
            #pragma unroll
            for (int i = 0; i < 8; i++) { N += snum[i]; D += sden[i]; }
            g_pnum[b * NCHK2 + ck] = N;
            g_pden[b * NCHK2 + ck] = D;
            __threadfence();                     // release partials before count
            atomicAdd(&g_done[b], 1u);
        }
    }
}

extern "C" void kernel_launch(void* const* d_in, const int* in_sizes, int n_in,
                              void* d_out, int out_size) {
    const float* x    = (const float*)d_in[0];
    const float* W_ih = (const float*)d_in[1];
    const float* b_ih = (const float*)d_in[2];
    const float* W_hh = (const float*)d_in[3];
    const float* b_hh = (const float*)d_in[4];
    const float* fc_w = (const float*)d_in[5];
    const float* fc_b = (const float*)d_in[6];
    float* out = (float*)d_out;
    (void)in_sizes; (void)n_in; (void)out_size;

    rnn_fused<<<BATCH + BATCH * RCHK, 256>>>(x, W_ih, b_ih, W_hh, b_hh, fc_w, fc_b, out);
}